// round 4
// baseline (speedup 1.0000x reference)
#include <cuda_runtime.h>

// BezierToImageLayer — sparse Gaussian splat, round 4.
// R4 vs R3 (69.7us):
//  - column-PAIR ownership: lane = (row residue mod 8) x (aligned col-pair residue mod 4)
//    -> LDS.64/STS.64 RMW (4 instrs vs 6, half the MIO ops). Aligned 8-col window
//    drops only cells with d>=3px (adds ~1e-5 abs err, budget 1e-3).
//  - fused exponent: g = exp2(C2*dx^2 + C2*dy^2): 2 MUFU/sample instead of 3.
//  - NSPLIT=8 (grid 2048, shorter CTAs -> smaller straggler wave) and combine fused
//    into the splat kernel via threadfence-reduction (last task of each batch sums
//    the 8 partials, clamps, writes out, resets the counter for graph replay).

#define BDIM     128
#define NWARPS   4
#define NSPLIT   8
#define WPIX     60
#define AROWS    67                         // rows -3..63
#define STRIDE   68                         // cols -4..63 ; 68/2=34 ≡ 2 (mod16): optimal LDS.64
#define RPAD     3
#define CPAD     4
#define NSAMP    30
#define NCURVE   160
#define CPT      (NCURVE / NSPLIT)          // 20 curves per task
#define CPW      (CPT / NWARPS)             // 5 curves per warp
#define COPY_W   (AROWS * STRIDE)           // 4556 floats
#define ACC_WORDS (NWARPS * COPY_W)         // 18224 floats = 72896 B

#define NBATCH   256
#define IMG      (WPIX * WPIX)

__device__ float g_scratch[NBATCH * NSPLIT * IMG];   // 29.5 MB partials (L2-hot)
__device__ int   g_cnt[NBATCH];                      // zero-init; reset by last CTA

__device__ __forceinline__ float ex2f(float a) {
    float r; asm("ex2.approx.f32 %0, %1;" : "=f"(r) : "f"(a)); return r;
}

__global__ __launch_bounds__(BDIM, 3)
void bezier_splat_kernel(const float* __restrict__ x, float* __restrict__ out)
{
    extern __shared__ float acc[];   // [NWARPS][AROWS][STRIDE], per-warp private

    const int task = blockIdx.x;          // 0..2047
    const int b    = task >> 3;
    const int part = task & (NSPLIT - 1);
    const int tid  = threadIdx.x;
    const int w    = tid >> 5;
    const int lane = tid & 31;

    // ---- zero private accumulators ----
    float4* az = (float4*)acc;
    for (int i = tid; i < ACC_WORDS / 4; i += BDIM)
        az[i] = make_float4(0.f, 0.f, 0.f, 0.f);
    __syncthreads();

    float* __restrict__ my = acc + w * COPY_W + RPAD * STRIDE + CPAD;

    const int ra3 = (lane >> 2) + 3;   // row residue (mod 8), pre-biased
    const int pc  = lane & 3;          // column-pair residue (mod 4)

    // ---- per-lane Bezier basis (lane == sample index n), pixel units ----
    const int   n  = (lane < NSAMP) ? lane : (NSAMP - 1);
    const float u  = (float)n * (1.0f / (float)NSAMP);
    const float t  = 2.0f*u*u*u - 3.0f*u*u + 2.0f*u;
    const float t2 = t * t;
    const float t3 = t2 * t;
    const float tb = 1.0f - t;
    const float b0 = 60.0f * t3;
    const float b1 = 180.0f * (t2 - t3);
    const float b2 = 180.0f * (t3 - 2.0f*t2 + t);
    const float b3 = 60.0f * tb * tb * tb;

    const float C2 = -2.0037431123457827f;   // -(5000/3600)*log2(e)

    const float* __restrict__ xb = x + ((size_t)b * NCURVE + part * CPT) * 8;

    for (int c = 0; c < CPW; ++c) {
        const int l = w + NWARPS * c;
        const float* ct = xb + l * 8;

        const float Xn = b0*ct[0] + b1*ct[2] + b2*ct[4] + b3*ct[6];
        const float Yn = b0*ct[1] + b1*ct[3] + b2*ct[5] + b3*ct[7];

        #pragma unroll 10
        for (int s = 0; s < NSAMP; ++s) {
            const float Xp = __shfl_sync(0xffffffffu, Xn, s);
            const float Yp = __shfl_sync(0xffffffffu, Yn, s);

            const int mi = (int)Xp;                 // in [0,59]
            const int mj = (int)Yp;

            // row: i in [mi-3, mi+4], i ≡ ra (mod 8)
            const int i  = mi - 3 + ((ra3 - mi) & 7);
            // col-pairs: P in [P0, P0+3], P ≡ pc (mod 4); cols 2P, 2P+1
            const int P0 = (mj - 3) >> 1;
            const int P  = P0 + ((pc - P0) & 3);

            const float dx  = (float)i       - Xp;
            const float dy1 = (float)(2 * P) - Yp;

            const float ax  = dx  * dx  * C2;
            const float ay1 = dy1 * dy1 * C2;
            const float e1  = ax + ay1;
            const float td  = fmaf(dy1, 2.0f * C2, C2);  // C2*(dy1+1)^2 - C2*dy1^2
            const float g1  = ex2f(e1);
            const float g2  = ex2f(e1 + td);

            float2* __restrict__ p = (float2*)(my + i * STRIDE + 2 * P);
            float2 v = *p;
            v.x += g1;
            v.y += g2;
            *p = v;
        }
    }
    __syncthreads();

    // ---- reduce 4 private copies -> scratch partial for this task ----
    float* __restrict__ sp = g_scratch + (size_t)task * IMG;
    const float* __restrict__ a0 = acc + RPAD * STRIDE + CPAD;
    for (int idx = tid; idx < IMG; idx += BDIM) {
        const int i = idx / WPIX;
        const int j = idx - i * WPIX;
        const int o = i * STRIDE + j;
        sp[idx] = a0[o] + a0[COPY_W + o] + a0[2*COPY_W + o] + a0[3*COPY_W + o];
    }

    // ---- last task of this batch combines the 8 partials ----
    __threadfence();
    __syncthreads();
    __shared__ int s_last;
    if (tid == 0) {
        int old = atomicAdd(&g_cnt[b], 1);
        s_last = (old == NSPLIT - 1);
    }
    __syncthreads();
    if (s_last) {
        __threadfence();   // acquire: see all tasks' scratch writes
        const float4* __restrict__ base =
            (const float4*)(g_scratch + (size_t)b * NSPLIT * IMG);
        float4* __restrict__ ob = (float4*)(out + (size_t)b * IMG);
        for (int q = tid; q < IMG / 4; q += BDIM) {
            float4 s0 = base[q];
            #pragma unroll
            for (int k = 1; k < NSPLIT; ++k) {
                const float4 v = base[k * (IMG / 4) + q];
                s0.x += v.x; s0.y += v.y; s0.z += v.z; s0.w += v.w;
            }
            s0.x = fminf(s0.x, 1.0f);
            s0.y = fminf(s0.y, 1.0f);
            s0.z = fminf(s0.z, 1.0f);
            s0.w = fminf(s0.w, 1.0f);
            ob[q] = s0;
        }
        if (tid == 0) g_cnt[b] = 0;   // reset for next graph replay
    }
}

extern "C" void kernel_launch(void* const* d_in, const int* in_sizes, int n_in,
                              void* d_out, int out_size)
{
    (void)in_sizes; (void)n_in; (void)out_size;
    const float* x = (const float*)d_in[0];
    float* out     = (float*)d_out;

    cudaFuncSetAttribute(bezier_splat_kernel,
                         cudaFuncAttributeMaxDynamicSharedMemorySize,
                         ACC_WORDS * (int)sizeof(float));

    bezier_splat_kernel<<<NBATCH * NSPLIT, BDIM, ACC_WORDS * (int)sizeof(float)>>>(x, out);
}